// round 8
// baseline (speedup 1.0000x reference)
#include <cuda_runtime.h>
#include <cuda_fp16.h>
#include <cfloat>

// Problem constants
#define NB    256     // batch
#define NN    1152    // input capsules
#define DIN   8       // input capsule dim
#define NC    10      // output capsules
#define NU    16      // output cap dim
#define TPB   512
#define KROWS 9       // rows per thread (1152 / 128 gg-groups)
#define WTOT  (NC * NN * DIN * NU)   // 1,474,560

// fp16 copy of W (2.95 MB) — static device scratch (allocation-free).
__device__ __align__(16) __half W_half[WTOT];

__global__ __launch_bounds__(512, 4)
void convert_W_kernel(const float* __restrict__ W)
{
    int i = blockIdx.x * blockDim.x + threadIdx.x;   // float4 index
    const int total4 = WTOT / 4;                      // 368,640
    for (; i < total4; i += gridDim.x * blockDim.x) {
        float4 w = reinterpret_cast<const float4*>(W)[i];
        __half2* dst = reinterpret_cast<__half2*>(W_half);
        dst[i * 2]     = __floats2half2_rn(w.x, w.y);
        dst[i * 2 + 1] = __floats2half2_rn(w.z, w.w);
    }
}

__global__ __launch_bounds__(TPB, 1)
void caps_routing_reg_kernel(const float* __restrict__ inp,
                             float* __restrict__ out)
{
    __shared__ float RED[16 * 32];   // [warp][batch(2)][u(16)] s-partials
    __shared__ float WRED[32];       // per-warp S partials [2][16]
    __shared__ float VS[32];         // v[2][16]

    const int t    = threadIdx.x;
    const int lane = t & 31;
    const int warp = t >> 5;
    const int u4   = t & 3;          // which 4-float u chunk this thread owns
    const int gg   = t >> 2;         // row group 0..127
    const int cc   = blockIdx.x;     // output capsule
    const int b0   = blockIdx.y << 1;

    float u0[KROWS][4], u1[KROWS][4];   // u_hat chunks, both batches
    float a0[KROWS], a1[KROWS];         // agreement logit deltas

    // ================= Phase 0: u_hat into registers (W in fp16) =================
    {
        const __half* Wc = W_half + (size_t)cc * (NN * DIN * NU);
        #pragma unroll
        for (int k = 0; k < KROWS; ++k) {
            const int n = gg + (k << 7);
            const float4* ip0 = reinterpret_cast<const float4*>(inp + ((size_t)b0       * NN + n) * DIN);
            const float4* ip1 = reinterpret_cast<const float4*>(inp + ((size_t)(b0 + 1) * NN + n) * DIN);
            float4 x0 = ip0[0], x1 = ip0[1];
            float4 y0 = ip1[0], y1 = ip1[1];
            float in0[8] = {x0.x, x0.y, x0.z, x0.w, x1.x, x1.y, x1.z, x1.w};
            float in1[8] = {y0.x, y0.y, y0.z, y0.w, y1.x, y1.y, y1.z, y1.w};
            // W[c][n][i][u4*4 .. +3] as 2x half2 per i
            const __half2* wp = reinterpret_cast<const __half2*>(Wc + (size_t)n * (DIN * NU)) + u4 * 2;
            float r0 = 0.f, r1 = 0.f, r2 = 0.f, r3 = 0.f;
            float q0 = 0.f, q1 = 0.f, q2 = 0.f, q3 = 0.f;
            #pragma unroll
            for (int i = 0; i < 8; ++i) {
                __half2 h01 = wp[i * 8];
                __half2 h23 = wp[i * 8 + 1];
                float2 f01 = __half22float2(h01);
                float2 f23 = __half22float2(h23);
                r0 += in0[i] * f01.x;  r1 += in0[i] * f01.y;
                r2 += in0[i] * f23.x;  r3 += in0[i] * f23.y;
                q0 += in1[i] * f01.x;  q1 += in1[i] * f01.y;
                q2 += in1[i] * f23.x;  q3 += in1[i] * f23.y;
            }
            u0[k][0] = r0; u0[k][1] = r1; u0[k][2] = r2; u0[k][3] = r3;
            u1[k][0] = q0; u1[k][1] = q1; u1[k][2] = q2; u1[k][3] = q3;
        }
    }

    // ================= Dynamic routing (3 iterations) =================
    // Initial logits b=1 drop out of softmax. Logits stay O(1), so no
    // max-subtraction is needed: cw = exp(a) directly; S summed in phase A.
    for (int it = 0; it < 3; ++it) {
        // ---- Phase A: s[u] partials + S partial ----
        {
            float s0[4] = {0.f, 0.f, 0.f, 0.f};
            float s1[4] = {0.f, 0.f, 0.f, 0.f};
            float ls0 = 0.f, ls1 = 0.f;
            #pragma unroll
            for (int k = 0; k < KROWS; ++k) {
                const float cw0 = (it == 0) ? 1.0f : __expf(a0[k]);
                const float cw1 = (it == 0) ? 1.0f : __expf(a1[k]);
                ls0 += cw0;  ls1 += cw1;
                #pragma unroll
                for (int j = 0; j < 4; ++j) {
                    s0[j] += cw0 * u0[k][j];
                    s1[j] += cw1 * u1[k][j];
                }
            }
            // butterfly over the 8 gg groups within this warp (same u4)
            #pragma unroll
            for (int off = 4; off <= 16; off <<= 1) {
                #pragma unroll
                for (int j = 0; j < 4; ++j) {
                    s0[j] += __shfl_xor_sync(0xffffffffu, s0[j], off);
                    s1[j] += __shfl_xor_sync(0xffffffffu, s1[j], off);
                }
                ls0 += __shfl_xor_sync(0xffffffffu, ls0, off);
                ls1 += __shfl_xor_sync(0xffffffffu, ls1, off);
            }
            if (lane < 4) {
                *reinterpret_cast<float4*>(&RED[warp * 32 +      u4 * 4]) = make_float4(s0[0], s0[1], s0[2], s0[3]);
                *reinterpret_cast<float4*>(&RED[warp * 32 + 16 + u4 * 4]) = make_float4(s1[0], s1[1], s1[2], s1[3]);
            }
            if (lane == 0) { WRED[warp] = ls0; WRED[16 + warp] = ls1; }
        }
        __syncthreads();

        // ---- Phase B: warp 0 finalizes s, squash -> v ----
        if (warp == 0) {
            const int q = lane >> 4;     // batch within pair
            const int u = lane & 15;
            float s = 0.f;
            #pragma unroll
            for (int w = 0; w < 16; ++w) s += RED[w * 32 + lane];
            float S;
            if (it == 0) S = (float)NN;
            else {
                S = 0.f;
                #pragma unroll
                for (int w = 0; w < 16; ++w) S += WRED[q * 16 + w];
            }
            s /= S;
            float sq = s * s;
            #pragma unroll
            for (int off = 1; off <= 8; off <<= 1) sq += __shfl_xor_sync(0xffffffffu, sq, off);
            const float scale = sq / ((1.0f + sq) * sqrtf(sq + 1e-9f));
            const float v = scale * s;
            VS[lane] = v;
            if (it == 2) out[((size_t)(b0 + q) * NC + cc) * NU + u] = v;
        }
        if (it == 2) return;
        __syncthreads();

        // ---- Phase C: agreement a[n] += u_hat[n] . v (quad reduction) ----
        {
            const float4 v0 = *reinterpret_cast<const float4*>(&VS[u4 * 4]);
            const float4 v1 = *reinterpret_cast<const float4*>(&VS[16 + u4 * 4]);
            #pragma unroll
            for (int k = 0; k < KROWS; ++k) {
                float d0 = u0[k][0] * v0.x + u0[k][1] * v0.y + u0[k][2] * v0.z + u0[k][3] * v0.w;
                float d1 = u1[k][0] * v1.x + u1[k][1] * v1.y + u1[k][2] * v1.z + u1[k][3] * v1.w;
                d0 += __shfl_xor_sync(0xffffffffu, d0, 1);
                d0 += __shfl_xor_sync(0xffffffffu, d0, 2);
                d1 += __shfl_xor_sync(0xffffffffu, d1, 1);
                d1 += __shfl_xor_sync(0xffffffffu, d1, 2);
                a0[k] = (it == 0) ? d0 : (a0[k] + d0);
                a1[k] = (it == 0) ? d1 : (a1[k] + d1);
            }
        }
        // no barrier needed: a[] is thread-private; VS reuse is fenced by
        // the phase-A sync before B rewrites it.
    }
}

extern "C" void kernel_launch(void* const* d_in, const int* in_sizes, int n_in,
                              void* d_out, int out_size)
{
    const float* inp = (const float*)d_in[0];
    const float* W   = (const float*)d_in[1];
    if (n_in >= 2 && in_sizes[0] == WTOT && in_sizes[1] == NB * NN * DIN) {
        const float* tmp = inp; inp = W; W = tmp;   // defensive order swap
    }
    float* out = (float*)d_out;

    // Step 1: W fp32 -> fp16 scratch (deterministic, runs every launch)
    convert_W_kernel<<<720, 512>>>(W);

    // Step 2: fused routing
    dim3 grid(NC, NB / 2);   // 10 x 128 = 1280 CTAs, one batch-pair each
    caps_routing_reg_kernel<<<grid, TPB>>>(inp, out);
}

// round 9
// speedup vs baseline: 1.5974x; 1.5974x over previous
#include <cuda_runtime.h>
#include <cuda_fp16.h>
#include <cfloat>

// Problem constants
#define NB    256     // batch
#define NN    1152    // input capsules
#define DIN   8       // input capsule dim
#define NC    10      // output capsules
#define NU    16      // output cap dim
#define TPB   512
#define KROWS 9       // rows per thread (1152 / 128 gg-groups)
#define WTOT  (NC * NN * DIN * NU)   // 1,474,560

// Permuted fp16 copy of W (2.95 MB), layout [c][n][u4][i][j]:
//   W2[(((c*NN + n)*4 + u4)*8 + i)*4 + j] = W[c][n][i][u4*4 + j]
// so each (n, u4) slice is 32 halves = 64 contiguous bytes = 4x float4.
__device__ __align__(16) __half W_half[WTOT];

__global__ __launch_bounds__(512, 4)
void convert_W_kernel(const float* __restrict__ W)
{
    const int total4 = WTOT / 4;                      // 368,640 float4s
    int idx = blockIdx.x * blockDim.x + threadIdx.x;  // = ((cn)*8 + i)*4 + u4
    for (; idx < total4; idx += gridDim.x * blockDim.x) {
        const int u4 = idx & 3;
        const int i  = (idx >> 2) & 7;
        const int cn = idx >> 5;
        float4 w = reinterpret_cast<const float4*>(W)[idx];   // W[c][n][i][u4*4..+3]
        __half2 h01 = __floats2half2_rn(w.x, w.y);
        __half2 h23 = __floats2half2_rn(w.z, w.w);
        const size_t d = (((size_t)cn * 4 + u4) * 8 + i) * 4; // half index
        __half2* dp = reinterpret_cast<__half2*>(W_half + d);
        dp[0] = h01;
        dp[1] = h23;
    }
}

__global__ __launch_bounds__(TPB, 1)
void caps_routing_reg_kernel(const float* __restrict__ inp,
                             float* __restrict__ out)
{
    __shared__ float RED[16 * 32];   // [warp][batch(2)][u(16)] s-partials
    __shared__ float WRED[32];       // per-warp S partials [2][16]
    __shared__ float VS[32];         // v[2][16]

    const int t    = threadIdx.x;
    const int lane = t & 31;
    const int warp = t >> 5;
    const int u4   = t & 3;          // which 4-float u chunk this thread owns
    const int gg   = t >> 2;         // row group 0..127
    const int cc   = blockIdx.x;     // output capsule
    const int b0   = blockIdx.y << 1;

    float u0[KROWS][4], u1[KROWS][4];   // u_hat chunks, both batches
    float a0[KROWS], a1[KROWS];         // agreement logits

    // ================= Phase 0: u_hat into registers =================
    // W slice per (n,u4) is 64 contiguous bytes -> 4x LDG.128, warp-coalesced.
    {
        const __half* Wc = W_half + (size_t)cc * (NN * DIN * NU);
        #pragma unroll
        for (int k = 0; k < KROWS; ++k) {
            const int n = gg + (k << 7);
            const float4* ip0 = reinterpret_cast<const float4*>(inp + ((size_t)b0       * NN + n) * DIN);
            const float4* ip1 = reinterpret_cast<const float4*>(inp + ((size_t)(b0 + 1) * NN + n) * DIN);
            float4 x0 = ip0[0], x1 = ip0[1];
            float4 y0 = ip1[0], y1 = ip1[1];
            float in0[8] = {x0.x, x0.y, x0.z, x0.w, x1.x, x1.y, x1.z, x1.w};
            float in1[8] = {y0.x, y0.y, y0.z, y0.w, y1.x, y1.y, y1.z, y1.w};

            const float4* wp = reinterpret_cast<const float4*>(Wc + ((size_t)n * 4 + u4) * 32);
            float r0 = 0.f, r1 = 0.f, r2 = 0.f, r3 = 0.f;
            float q0 = 0.f, q1 = 0.f, q2 = 0.f, q3 = 0.f;
            #pragma unroll
            for (int m = 0; m < 4; ++m) {
                float4 wq = wp[m];   // halves: i=2m (j0..3), i=2m+1 (j0..3)
                const __half2* hh = reinterpret_cast<const __half2*>(&wq);
                float2 fa = __half22float2(hh[0]);   // i=2m,   j0 j1
                float2 fb = __half22float2(hh[1]);   // i=2m,   j2 j3
                float2 fc = __half22float2(hh[2]);   // i=2m+1, j0 j1
                float2 fd = __half22float2(hh[3]);   // i=2m+1, j2 j3
                const float xa0 = in0[2 * m], xa1 = in0[2 * m + 1];
                const float xb0 = in1[2 * m], xb1 = in1[2 * m + 1];
                r0 += xa0 * fa.x + xa1 * fc.x;
                r1 += xa0 * fa.y + xa1 * fc.y;
                r2 += xa0 * fb.x + xa1 * fd.x;
                r3 += xa0 * fb.y + xa1 * fd.y;
                q0 += xb0 * fa.x + xb1 * fc.x;
                q1 += xb0 * fa.y + xb1 * fc.y;
                q2 += xb0 * fb.x + xb1 * fd.x;
                q3 += xb0 * fb.y + xb1 * fd.y;
            }
            u0[k][0] = r0; u0[k][1] = r1; u0[k][2] = r2; u0[k][3] = r3;
            u1[k][0] = q0; u1[k][1] = q1; u1[k][2] = q2; u1[k][3] = q3;
        }
    }

    // ================= Dynamic routing (3 iterations) =================
    // Initial logits b=1 drop out of softmax. Logits stay O(1): no max
    // subtraction needed; cw = exp(a), S summed alongside in phase A.
    for (int it = 0; it < 3; ++it) {
        // ---- Phase A: s[u] partials + S partial ----
        {
            float s0[4] = {0.f, 0.f, 0.f, 0.f};
            float s1[4] = {0.f, 0.f, 0.f, 0.f};
            float ls0 = 0.f, ls1 = 0.f;
            #pragma unroll
            for (int k = 0; k < KROWS; ++k) {
                const float cw0 = (it == 0) ? 1.0f : __expf(a0[k]);
                const float cw1 = (it == 0) ? 1.0f : __expf(a1[k]);
                ls0 += cw0;  ls1 += cw1;
                #pragma unroll
                for (int j = 0; j < 4; ++j) {
                    s0[j] += cw0 * u0[k][j];
                    s1[j] += cw1 * u1[k][j];
                }
            }
            // butterfly over the 8 gg groups within this warp (same u4)
            #pragma unroll
            for (int off = 4; off <= 16; off <<= 1) {
                #pragma unroll
                for (int j = 0; j < 4; ++j) {
                    s0[j] += __shfl_xor_sync(0xffffffffu, s0[j], off);
                    s1[j] += __shfl_xor_sync(0xffffffffu, s1[j], off);
                }
                ls0 += __shfl_xor_sync(0xffffffffu, ls0, off);
                ls1 += __shfl_xor_sync(0xffffffffu, ls1, off);
            }
            if (lane < 4) {
                *reinterpret_cast<float4*>(&RED[warp * 32 +      u4 * 4]) = make_float4(s0[0], s0[1], s0[2], s0[3]);
                *reinterpret_cast<float4*>(&RED[warp * 32 + 16 + u4 * 4]) = make_float4(s1[0], s1[1], s1[2], s1[3]);
            }
            if (lane == 0) { WRED[warp] = ls0; WRED[16 + warp] = ls1; }
        }
        __syncthreads();

        // ---- Phase B: warp 0 finalizes s, squash -> v ----
        if (warp == 0) {
            const int q = lane >> 4;     // batch within pair
            const int u = lane & 15;
            float s = 0.f;
            #pragma unroll
            for (int w = 0; w < 16; ++w) s += RED[w * 32 + lane];
            float S;
            if (it == 0) S = (float)NN;
            else {
                S = 0.f;
                #pragma unroll
                for (int w = 0; w < 16; ++w) S += WRED[q * 16 + w];
            }
            s /= S;
            float sq = s * s;
            #pragma unroll
            for (int off = 1; off <= 8; off <<= 1) sq += __shfl_xor_sync(0xffffffffu, sq, off);
            const float scale = sq / ((1.0f + sq) * sqrtf(sq + 1e-9f));
            const float v = scale * s;
            VS[lane] = v;
            if (it == 2) out[((size_t)(b0 + q) * NC + cc) * NU + u] = v;
        }
        if (it == 2) return;
        __syncthreads();

        // ---- Phase C: agreement a[n] += u_hat[n] . v (quad reduction) ----
        {
            const float4 v0 = *reinterpret_cast<const float4*>(&VS[u4 * 4]);
            const float4 v1 = *reinterpret_cast<const float4*>(&VS[16 + u4 * 4]);
            #pragma unroll
            for (int k = 0; k < KROWS; ++k) {
                float d0 = u0[k][0] * v0.x + u0[k][1] * v0.y + u0[k][2] * v0.z + u0[k][3] * v0.w;
                float d1 = u1[k][0] * v1.x + u1[k][1] * v1.y + u1[k][2] * v1.z + u1[k][3] * v1.w;
                d0 += __shfl_xor_sync(0xffffffffu, d0, 1);
                d0 += __shfl_xor_sync(0xffffffffu, d0, 2);
                d1 += __shfl_xor_sync(0xffffffffu, d1, 1);
                d1 += __shfl_xor_sync(0xffffffffu, d1, 2);
                a0[k] = (it == 0) ? d0 : (a0[k] + d0);
                a1[k] = (it == 0) ? d1 : (a1[k] + d1);
            }
        }
        // a[] is thread-private; VS reuse is fenced by the phase-A sync.
    }
}

extern "C" void kernel_launch(void* const* d_in, const int* in_sizes, int n_in,
                              void* d_out, int out_size)
{
    const float* inp = (const float*)d_in[0];
    const float* W   = (const float*)d_in[1];
    if (n_in >= 2 && in_sizes[0] == WTOT && in_sizes[1] == NB * NN * DIN) {
        const float* tmp = inp; inp = W; W = tmp;   // defensive order swap
    }
    float* out = (float*)d_out;

    // Step 1: W fp32 -> permuted fp16 scratch
    convert_W_kernel<<<720, 512>>>(W);

    // Step 2: fused routing
    dim3 grid(NC, NB / 2);   // 10 x 128 = 1280 CTAs, one batch-pair each
    caps_routing_reg_kernel<<<grid, TPB>>>(inp, out);
}

// round 11
// speedup vs baseline: 2.0196x; 1.2643x over previous
#include <cuda_runtime.h>
#include <cuda_fp16.h>
#include <cfloat>

// Problem constants
#define NB    256     // batch
#define NN    1152    // input capsules
#define DIN   8       // input capsule dim
#define NC    10      // output capsules
#define NU    16      // output cap dim
#define TPB   512
#define KROWS 9       // rows per thread (1152 / 128 gg-groups)
#define WTOT  (NC * NN * DIN * NU)   // 1,474,560 halves

// Warp-contiguous permuted fp16 W (2.95 MB).
// 16-byte chunk index: ((((c*9 + k)*16 + w)*4 + m)*8 + g3)*4 + u4
//   holds W[c][n][2m][u4*4..+3] , W[c][n][2m+1][u4*4..+3]   (8 halves)
//   where n = k*128 + w*8 + g3.
// For fixed (k,m), a warp's 32 lanes (g3=lane>>2, u4=lane&3) hit 32
// CONSECUTIVE chunks = 512B = 4 cache lines per LDG.128. Ideal coalescing.
__device__ __align__(16) __half W_half[WTOT];

__global__ __launch_bounds__(512, 4)
void convert_W_kernel(const float* __restrict__ W)
{
    const int nchunks = WTOT / 8;                     // 184,320 16B-chunks
    int o = blockIdx.x * blockDim.x + threadIdx.x;
    for (; o < nchunks; o += gridDim.x * blockDim.x) {
        const int u4 = o & 3;
        const int g3 = (o >> 2) & 7;
        const int m  = (o >> 5) & 3;
        const int w  = (o >> 7) & 15;
        const int ck = o >> 11;          // c*9 + k
        const int k  = ck % 9;
        const int c  = ck / 9;
        const int n  = k * 128 + w * 8 + g3;
        const int i0 = 2 * m;
        // source float4 index for W[c][n][i][u4*4..+3] = ((c*NN+n)*8 + i)*4 + u4
        const size_t s0 = (((size_t)c * NN + n) * 8 + i0) * 4 + u4;
        float4 wa = reinterpret_cast<const float4*>(W)[s0];
        float4 wb = reinterpret_cast<const float4*>(W)[s0 + 4];   // i0+1
        __half2 h[4];
        h[0] = __floats2half2_rn(wa.x, wa.y);
        h[1] = __floats2half2_rn(wa.z, wa.w);
        h[2] = __floats2half2_rn(wb.x, wb.y);
        h[3] = __floats2half2_rn(wb.z, wb.w);
        reinterpret_cast<float4*>(W_half)[o] = *reinterpret_cast<float4*>(h);
    }
}

__global__ __launch_bounds__(TPB, 1)
void caps_routing_reg_kernel(const float* __restrict__ inp,
                             float* __restrict__ out)
{
    __shared__ float RED[16 * 32];   // [warp][batch(2)][u(16)] s-partials
    __shared__ float WRED[32];       // per-warp S partials [2][16]
    __shared__ float VS[32];         // v[2][16]

    const int t    = threadIdx.x;
    const int lane = t & 31;
    const int warp = t >> 5;
    const int u4   = t & 3;          // u chunk this thread owns
    const int gg   = t >> 2;         // row group 0..127  (= warp*8 + g3)
    const int cc   = blockIdx.x;     // output capsule
    const int b0   = blockIdx.y << 1;

    float u0[KROWS][4], u1[KROWS][4];   // u_hat chunks, both batches
    float a0[KROWS], a1[KROWS];         // agreement logits

    // ================= Phase 0: u_hat into registers =================
    {
        // per-thread W chunk base in float4 units: see layout comment above.
        // idx(k,m) = (((cc*9 + k)*16 + warp)*4 + m)*32 + lane
        const float4* W4 = reinterpret_cast<const float4*>(W_half);
        #pragma unroll
        for (int k = 0; k < KROWS; ++k) {
            const int n = gg + (k << 7);
            const float4* ip0 = reinterpret_cast<const float4*>(inp + ((size_t)b0       * NN + n) * DIN);
            const float4* ip1 = reinterpret_cast<const float4*>(inp + ((size_t)(b0 + 1) * NN + n) * DIN);
            float4 x0 = ip0[0], x1 = ip0[1];
            float4 y0 = ip1[0], y1 = ip1[1];
            float in0[8] = {x0.x, x0.y, x0.z, x0.w, x1.x, x1.y, x1.z, x1.w};
            float in1[8] = {y0.x, y0.y, y0.z, y0.w, y1.x, y1.y, y1.z, y1.w};

            const size_t wbase = ((((size_t)cc * 9 + k) * 16 + warp) * 4) * 32 + lane;
            float r0 = 0.f, r1 = 0.f, r2 = 0.f, r3 = 0.f;
            float q0 = 0.f, q1 = 0.f, q2 = 0.f, q3 = 0.f;
            #pragma unroll
            for (int m = 0; m < 4; ++m) {
                float4 wq = W4[wbase + m * 32];  // warp-contiguous 512B
                const __half2* hh = reinterpret_cast<const __half2*>(&wq);
                float2 fa = __half22float2(hh[0]);   // i=2m,   j0 j1
                float2 fb = __half22float2(hh[1]);   // i=2m,   j2 j3
                float2 fc = __half22float2(hh[2]);   // i=2m+1, j0 j1
                float2 fd = __half22float2(hh[3]);   // i=2m+1, j2 j3
                const float xa0 = in0[2 * m], xa1 = in0[2 * m + 1];
                const float xb0 = in1[2 * m], xb1 = in1[2 * m + 1];
                r0 += xa0 * fa.x + xa1 * fc.x;
                r1 += xa0 * fa.y + xa1 * fc.y;
                r2 += xa0 * fb.x + xa1 * fd.x;
                r3 += xa0 * fb.y + xa1 * fd.y;
                q0 += xb0 * fa.x + xb1 * fc.x;
                q1 += xb0 * fa.y + xb1 * fc.y;
                q2 += xb0 * fb.x + xb1 * fd.x;
                q3 += xb0 * fb.y + xb1 * fd.y;
            }
            u0[k][0] = r0; u0[k][1] = r1; u0[k][2] = r2; u0[k][3] = r3;
            u1[k][0] = q0; u1[k][1] = q1; u1[k][2] = q2; u1[k][3] = q3;
        }
    }

    // ================= Dynamic routing (3 iterations) =================
    // Initial logits b=1 drop out of softmax. Logits stay O(1): cw = exp(a)
    // directly (no max subtraction); S summed alongside in phase A.
    for (int it = 0; it < 3; ++it) {
        // ---- Phase A: s[u] partials + S partial ----
        {
            float s0[4] = {0.f, 0.f, 0.f, 0.f};
            float s1[4] = {0.f, 0.f, 0.f, 0.f};
            float ls0 = 0.f, ls1 = 0.f;
            #pragma unroll
            for (int k = 0; k < KROWS; ++k) {
                const float cw0 = (it == 0) ? 1.0f : __expf(a0[k]);
                const float cw1 = (it == 0) ? 1.0f : __expf(a1[k]);
                ls0 += cw0;  ls1 += cw1;
                #pragma unroll
                for (int j = 0; j < 4; ++j) {
                    s0[j] += cw0 * u0[k][j];
                    s1[j] += cw1 * u1[k][j];
                }
            }
            // butterfly over the 8 gg groups within this warp (same u4)
            #pragma unroll
            for (int off = 4; off <= 16; off <<= 1) {
                #pragma unroll
                for (int j = 0; j < 4; ++j) {
                    s0[j] += __shfl_xor_sync(0xffffffffu, s0[j], off);
                    s1[j] += __shfl_xor_sync(0xffffffffu, s1[j], off);
                }
                ls0 += __shfl_xor_sync(0xffffffffu, ls0, off);
                ls1 += __shfl_xor_sync(0xffffffffu, ls1, off);
            }
            if (lane < 4) {
                *reinterpret_cast<float4*>(&RED[warp * 32 +      u4 * 4]) = make_float4(s0[0], s0[1], s0[2], s0[3]);
                *reinterpret_cast<float4*>(&RED[warp * 32 + 16 + u4 * 4]) = make_float4(s1[0], s1[1], s1[2], s1[3]);
            }
            if (lane == 0) { WRED[warp] = ls0; WRED[16 + warp] = ls1; }
        }
        __syncthreads();

        // ---- Phase B: warp 0 finalizes s, squash -> v ----
        if (warp == 0) {
            const int q = lane >> 4;     // batch within pair
            const int u = lane & 15;
            float s = 0.f;
            #pragma unroll
            for (int w = 0; w < 16; ++w) s += RED[w * 32 + lane];
            float S;
            if (it == 0) S = (float)NN;
            else {
                S = 0.f;
                #pragma unroll
                for (int w = 0; w < 16; ++w) S += WRED[q * 16 + w];
            }
            s /= S;
            float sq = s * s;
            #pragma unroll
            for (int off = 1; off <= 8; off <<= 1) sq += __shfl_xor_sync(0xffffffffu, sq, off);
            const float scale = sq / ((1.0f + sq) * sqrtf(sq + 1e-9f));
            const float v = scale * s;
            VS[lane] = v;
            if (it == 2) out[((size_t)(b0 + q) * NC + cc) * NU + u] = v;
        }
        if (it == 2) return;
        __syncthreads();

        // ---- Phase C: agreement a[n] += u_hat[n] . v (quad reduction) ----
        {
            const float4 v0 = *reinterpret_cast<const float4*>(&VS[u4 * 4]);
            const float4 v1 = *reinterpret_cast<const float4*>(&VS[16 + u4 * 4]);
            #pragma unroll
            for (int k = 0; k < KROWS; ++k) {
                float d0 = u0[k][0] * v0.x + u0[k][1] * v0.y + u0[k][2] * v0.z + u0[k][3] * v0.w;
                float d1 = u1[k][0] * v1.x + u1[k][1] * v1.y + u1[k][2] * v1.z + u1[k][3] * v1.w;
                d0 += __shfl_xor_sync(0xffffffffu, d0, 1);
                d0 += __shfl_xor_sync(0xffffffffu, d0, 2);
                d1 += __shfl_xor_sync(0xffffffffu, d1, 1);
                d1 += __shfl_xor_sync(0xffffffffu, d1, 2);
                a0[k] = (it == 0) ? d0 : (a0[k] + d0);
                a1[k] = (it == 0) ? d1 : (a1[k] + d1);
            }
        }
        // a[] is thread-private; VS reuse is fenced by the phase-A sync.
    }
}

extern "C" void kernel_launch(void* const* d_in, const int* in_sizes, int n_in,
                              void* d_out, int out_size)
{
    const float* inp = (const float*)d_in[0];
    const float* W   = (const float*)d_in[1];
    if (n_in >= 2 && in_sizes[0] == WTOT && in_sizes[1] == NB * NN * DIN) {
        const float* tmp = inp; inp = W; W = tmp;   // defensive order swap
    }
    float* out = (float*)d_out;

    // Step 1: W fp32 -> warp-contiguous fp16 scratch
    convert_W_kernel<<<720, 512>>>(W);

    // Step 2: fused routing
    dim3 grid(NC, NB / 2);   // 10 x 128 = 1280 CTAs, one batch-pair each
    caps_routing_reg_kernel<<<grid, TPB>>>(inp, out);
}